// round 11
// baseline (speedup 1.0000x reference)
#include <cuda_runtime.h>
#include <cuda_bf16.h>
#include <cstdint>
#include <math.h>

#define B_TOTAL 32768
#define NSLOT   5
#define D_IN    512
#define DK      16
#define NV      7
#define MT      256          // batches per block
#define NCHK    (D_IN / 16)  // 32 k-chunks of 16
#define THREADS 256

// dynamic smem: [0 .. 16384) words: uint4 B fragments (64KB);
//               [16384 .. 24576) words: raw W (32KB)  -> total 96KB
#define RAW_OFF_W   16384            // word offset of raw W
#define SMEM_BYTES  (96 * 1024)

// projection scratch: P[v][b][k]; v: 0,1 = read slots; 2..6 = write slots
__device__ float g_P[NV][B_TOTAL][DK];

static __device__ __forceinline__ uint32_t tf32_of(float x) {
    uint32_t r; asm("cvt.rna.tf32.f32 %0, %1;" : "=r"(r) : "f"(x)); return r;
}
// 2-way split: x = as_float(h) + as_float(l) + O(2^-24 x) residual after hh+hl+lh
static __device__ __forceinline__ void split2(float x, uint32_t& h, uint32_t& l) {
    h = tf32_of(x);
    l = tf32_of(x - __uint_as_float(h));
}
static __device__ __forceinline__ void mma16808(float* d, const uint32_t* a,
                                                uint32_t b0, uint32_t b1) {
    asm volatile(
        "mma.sync.aligned.m16n8k8.row.col.f32.tf32.tf32.f32 "
        "{%0,%1,%2,%3}, {%4,%5,%6,%7}, {%8,%9}, {%0,%1,%2,%3};"
        : "+f"(d[0]), "+f"(d[1]), "+f"(d[2]), "+f"(d[3])
        : "r"(a[0]), "r"(a[1]), "r"(a[2]), "r"(a[3]), "r"(b0), "r"(b1));
}

// ---------------------------------------------------------------------------
// Kernel 1: projection GEMM on mma.m16n8k8.tf32, fp32 via 2-way split,
// THREE passes (hh, hl, lh; ll dropped — 2^-24 rel, ~1e-8 abs score error).
// grid = (128, 7), 256 threads (8 warps x 32 batches each).
//
// K-permutation: memory col d = c*16 + 4*t4 + s, where s = 2*ks + reg and
// fragment slot reg0 -> kf=t4, reg1 -> kf=t4+4. A loads become one float4 per
// (row, chunk): (x,y) feed ks=0, (z,w) feed ks=1. B staged in fragment order.
// ---------------------------------------------------------------------------
__global__ __launch_bounds__(THREADS) void proj_kernel(
    const float* __restrict__ q, const float* __restrict__ kk,
    const float* __restrict__ wr, const float* __restrict__ ww)
{
    extern __shared__ uint32_t sh[];
    uint4* sFrag = (uint4*)sh;                       // [c][ks][nt][lane] -> {h0,h1,l0,l1}
    float* sRaw  = (float*)(sh + RAW_OFF_W);         // raw W, 8192 floats

    const int tid  = threadIdx.x;
    const int lane = tid & 31;
    const int wid  = tid >> 5;
    const int g    = lane >> 2;
    const int t4   = lane & 3;

    const int v = blockIdx.y;
    const float* src; const float* W; int slot;
    if (v < 2) { src = q;  slot = v;     W = wr + (size_t)v * D_IN * DK; }
    else       { src = kk; slot = v - 2; W = ww + (size_t)(v - 2) * D_IN * DK; }
    const int bbase = blockIdx.x * MT;

    // ---- phase 0: coalesced raw copy of W (8192 floats) ----
    {
        const float4* Ws = (const float4*)W;
        float4*       Wd = (float4*)sRaw;
        #pragma unroll
        for (int i = 0; i < 8; i++) Wd[tid + i * THREADS] = Ws[tid + i * THREADS];
    }
    __syncthreads();

    // ---- phase 1: scatter-convert W into fragment order ----
    #pragma unroll
    for (int t = 0; t < 16; t++) {
        int j   = tid + t * THREADS;          // 0..4095  = ((c*2+ks)*2+nt)*32+lane
        int jt4 = j & 3;
        int jg  = (j >> 2) & 7;
        int nt  = (j >> 5) & 1;
        int ks  = (j >> 6) & 1;
        int c   = j >> 7;
        int d0  = c * 16 + 4 * jt4 + 2 * ks;  // reg 0
        int n   = nt * 8 + jg;
        float w0 = sRaw[d0 * DK + n];
        float w1 = sRaw[(d0 + 1) * DK + n];
        uint4 V;
        split2(w0, V.x, V.z);
        split2(w1, V.y, V.w);
        sFrag[j] = V;                          // {h(b0), h(b1), l(b0), l(b1)}
    }
    __syncthreads();

    // A pointers: warp rows wid*32 + {g, g+8, g+16, g+24}
    const float* ap[4];
    #pragma unroll
    for (int rh = 0; rh < 4; rh++) {
        int row = bbase + wid * 32 + rh * 8 + g;
        ap[rh] = src + (size_t)row * (NSLOT * D_IN) + (size_t)slot * D_IN + t4 * 4;
    }

    float acc[2][2][4];
    #pragma unroll
    for (int mt = 0; mt < 2; mt++)
        #pragma unroll
        for (int nt = 0; nt < 2; nt++)
            #pragma unroll
            for (int jj = 0; jj < 4; jj++) acc[mt][nt][jj] = 0.0f;

    // prefetch chunk 0
    float4 f[4], pf[4];
    #pragma unroll
    for (int rh = 0; rh < 4; rh++) f[rh] = *(const float4*)(ap[rh]);

    #pragma unroll 2
    for (int c = 0; c < NCHK; c++) {
        // prefetch next chunk while computing this one
        if (c + 1 < NCHK) {
            #pragma unroll
            for (int rh = 0; rh < 4; rh++)
                pf[rh] = *(const float4*)(ap[rh] + (c + 1) * 16);
        }

        #pragma unroll
        for (int ks = 0; ks < 2; ks++) {
            // A fragments for this ks: a0=(g,t4), a1=(g+8,t4), a2=(g,t4+4), a3=(g+8,t4+4)
            uint32_t ah[2][4], al[2][4];
            #pragma unroll
            for (int mt = 0; mt < 2; mt++) {
                const float4 flo = f[2 * mt];
                const float4 fhi = f[2 * mt + 1];
                float e0 = ks ? flo.z : flo.x;
                float e1 = ks ? fhi.z : fhi.x;
                float e2 = ks ? flo.w : flo.y;
                float e3 = ks ? fhi.w : fhi.y;
                split2(e0, ah[mt][0], al[mt][0]);
                split2(e1, ah[mt][1], al[mt][1]);
                split2(e2, ah[mt][2], al[mt][2]);
                split2(e3, ah[mt][3], al[mt][3]);
            }
            #pragma unroll
            for (int nt = 0; nt < 2; nt++) {
                uint4 V = sFrag[((c * 2 + ks) * 2 + nt) * 32 + lane];
                #pragma unroll
                for (int mt = 0; mt < 2; mt++) {
                    mma16808(acc[mt][nt], ah[mt], V.x, V.y);   // hh
                    mma16808(acc[mt][nt], ah[mt], V.z, V.w);   // hl
                    mma16808(acc[mt][nt], al[mt], V.x, V.y);   // lh
                    // ll dropped: 2^-24 relative, far below argmax margin
                }
            }
        }

        #pragma unroll
        for (int rh = 0; rh < 4; rh++) f[rh] = pf[rh];
    }

    // write D: c0,c1 = row g cols t4*2,+1 ; c2,c3 = row g+8
    #pragma unroll
    for (int mt = 0; mt < 2; mt++) {
        int r0 = bbase + wid * 32 + mt * 16 + g;
        #pragma unroll
        for (int nt = 0; nt < 2; nt++) {
            int col = nt * 8 + t4 * 2;
            *(float2*)&g_P[v][r0][col]     = make_float2(acc[mt][nt][0], acc[mt][nt][1]);
            *(float2*)&g_P[v][r0 + 8][col] = make_float2(acc[mt][nt][2], acc[mt][nt][3]);
        }
    }
}

// ---------------------------------------------------------------------------
// Kernel 2: scores + threefry gumbel + argmax -> one-hot (2 threads per batch)
// ---------------------------------------------------------------------------
__device__ __forceinline__ uint32_t rotl32(uint32_t x, int r) {
    return (x << r) | (x >> (32 - r));
}

__device__ __forceinline__ uint32_t threefry_bits(uint32_t key, uint32_t ctr)
{
    const uint32_t ks0 = 0u, ks1 = key, ks2 = 0x1BD11BDAu ^ key;
    uint32_t x0 = ks0;
    uint32_t x1 = ctr + ks1;
#define R4(a,b,cc,d)                                   \
    x0 += x1; x1 = rotl32(x1,(a));  x1 ^= x0;          \
    x0 += x1; x1 = rotl32(x1,(b));  x1 ^= x0;          \
    x0 += x1; x1 = rotl32(x1,(cc)); x1 ^= x0;          \
    x0 += x1; x1 = rotl32(x1,(d));  x1 ^= x0;
    R4(13,15,26,6);   x0 += ks1; x1 += ks2 + 1u;
    R4(17,29,16,24);  x0 += ks2; x1 += ks0 + 2u;
    R4(13,15,26,6);   x0 += ks0; x1 += ks1 + 3u;
    R4(17,29,16,24);  x0 += ks1; x1 += ks2 + 4u;
    R4(13,15,26,6);   x0 += ks2; x1 += ks0 + 5u;
#undef R4
    return x0 ^ x1;
}

__device__ __forceinline__ float gumbel_from_bits(uint32_t bits)
{
    float u = __uint_as_float((bits >> 9) | 0x3f800000u) - 1.0f;
    float val = fmaxf(1e-10f, u * (1.0f - 1e-10f) + 1e-10f);
    return -logf(-logf(val));
}

__global__ __launch_bounds__(128) void score_kernel(float* __restrict__ out)
{
    const int idx = blockIdx.x * blockDim.x + threadIdx.x;
    const int b = idx >> 1;
    const int r = idx & 1;
    if (b >= B_TOTAL) return;

    float rv[DK];
    #pragma unroll
    for (int t = 0; t < 4; t++)
        ((float4*)rv)[t] = ((const float4*)&g_P[r][b][0])[t];

    float z[NSLOT];
    #pragma unroll
    for (int m = 0; m < NSLOT; m++) {
        float wv[DK];
        #pragma unroll
        for (int t = 0; t < 4; t++)
            ((float4*)wv)[t] = ((const float4*)&g_P[2 + m][b][0])[t];

        float s = 0.0f;
        #pragma unroll
        for (int t = 0; t < DK; t++) s = fmaf(rv[t], wv[t], s);
        s *= 0.25f;

        const uint32_t ctr = (uint32_t)(b * NSLOT + m);
        z[m] = s + gumbel_from_bits(threefry_bits(42u + (uint32_t)r, ctr));
    }

    int a0 = 0; float bv = z[0];
    #pragma unroll
    for (int m = 1; m < NSLOT; m++)
        if (z[m] > bv) { bv = z[m]; a0 = m; }

    float* o = out + (size_t)r * B_TOTAL * NSLOT + (size_t)b * NSLOT;
    #pragma unroll
    for (int m = 0; m < NSLOT; m++) o[m] = (m == a0) ? 1.0f : 0.0f;
}

// ---------------------------------------------------------------------------
extern "C" void kernel_launch(void* const* d_in, const int* in_sizes, int n_in,
                              void* d_out, int out_size)
{
    const float* q  = (const float*)d_in[0];
    const float* kk = (const float*)d_in[1];
    const float* wr = (const float*)d_in[2];
    const float* ww = (const float*)d_in[3];
    float* out = (float*)d_out;

    cudaFuncSetAttribute(proj_kernel,
                         cudaFuncAttributeMaxDynamicSharedMemorySize, SMEM_BYTES);

    dim3 grid1(B_TOTAL / MT, NV);
    proj_kernel<<<grid1, THREADS, SMEM_BYTES>>>(q, kk, wr, ww);

    score_kernel<<<(2 * B_TOTAL) / 128, 128>>>(out);
}

// round 12
// speedup vs baseline: 1.0985x; 1.0985x over previous
#include <cuda_runtime.h>
#include <cuda_bf16.h>
#include <cstdint>
#include <math.h>

#define B_TOTAL 32768
#define NSLOT   5
#define D_IN    512
#define DK      16
#define NV      7
#define MT      256          // batches per block
#define NCHK    (D_IN / 16)  // 32 k-chunks of 16
#define THREADS 256

// dynamic smem: sFrag only — [c][ks][nt][lane] uint4 = 4096 * 16B = 64KB
#define SMEM_BYTES  65536

// projection scratch: P[v][b][k]; v: 0,1 = read slots; 2..6 = write slots
__device__ float g_P[NV][B_TOTAL][DK];

static __device__ __forceinline__ uint32_t tf32_of(float x) {
    uint32_t r; asm("cvt.rna.tf32.f32 %0, %1;" : "=r"(r) : "f"(x)); return r;
}
// 2-way split: x = as_float(h) + as_float(l); hh+hl+lh leaves O(2^-24 x) residual
static __device__ __forceinline__ void split2(float x, uint32_t& h, uint32_t& l) {
    h = tf32_of(x);
    l = tf32_of(x - __uint_as_float(h));
}
static __device__ __forceinline__ void mma16808(float* d, const uint32_t* a,
                                                uint32_t b0, uint32_t b1) {
    asm volatile(
        "mma.sync.aligned.m16n8k8.row.col.f32.tf32.tf32.f32 "
        "{%0,%1,%2,%3}, {%4,%5,%6,%7}, {%8,%9}, {%0,%1,%2,%3};"
        : "+f"(d[0]), "+f"(d[1]), "+f"(d[2]), "+f"(d[3])
        : "r"(a[0]), "r"(a[1]), "r"(a[2]), "r"(a[3]), "r"(b0), "r"(b1));
}

// ---------------------------------------------------------------------------
// Kernel 1: projection GEMM on mma.m16n8k8.tf32, fp32 via 2-way split,
// 3 passes (hh, hl, lh). grid = (128, 7), 256 threads, 3 blocks/SM.
//
// K-permutation: memory col d = c*16 + 4*t4 + 2*ks + reg; A loads collapse to
// one float4 per (row, chunk). W converted gmem->fragment order directly:
// thread j reads W[2*jj*16+n], W[(2*jj+1)*16+n] (coalesced) and scatter-STS's
// the uint4 fragment {h0,h1,l0,l1}.
// ---------------------------------------------------------------------------
__global__ __launch_bounds__(THREADS, 3) void proj_kernel(
    const float* __restrict__ q, const float* __restrict__ kk,
    const float* __restrict__ wr, const float* __restrict__ ww)
{
    extern __shared__ uint32_t sh[];
    uint4* sFrag = (uint4*)sh;           // [c][ks][nt][lane] -> {h0,h1,l0,l1}

    const int tid  = threadIdx.x;
    const int lane = tid & 31;
    const int wid  = tid >> 5;
    const int g    = lane >> 2;
    const int t4   = lane & 3;

    const int v = blockIdx.y;
    const float* src; const float* W; int slot;
    if (v < 2) { src = q;  slot = v;     W = wr + (size_t)v * D_IN * DK; }
    else       { src = kk; slot = v - 2; W = ww + (size_t)(v - 2) * D_IN * DK; }
    const int bbase = blockIdx.x * MT;

    // ---- W -> fragment conversion, coalesced gmem reads, scattered STS ----
    #pragma unroll
    for (int t = 0; t < 16; t++) {
        int j  = tid + t * THREADS;      // 0..4095
        int n  = j & 15;
        int jj = j >> 4;                 // 0..255 ; d0 = 2*jj
        float w0 = W[jj * 32 + n];       // W[d0][n]
        float w1 = W[jj * 32 + 16 + n];  // W[d0+1][n]
        uint4 V;
        split2(w0, V.x, V.z);
        split2(w1, V.y, V.w);
        int c   = jj >> 3;
        int rem = jj & 7;                // = 2*jt4 + ks
        int jt4 = rem >> 1;
        int ks  = rem & 1;
        int nt  = n >> 3;
        int ln  = (n & 7) * 4 + jt4;     // fragment lane = g*4 + t4
        sFrag[((c * 2 + ks) * 2 + nt) * 32 + ln] = V;
    }
    __syncthreads();

    // A pointers: warp rows wid*32 + {g, g+8, g+16, g+24}
    const float* ap[4];
    #pragma unroll
    for (int rh = 0; rh < 4; rh++) {
        int row = bbase + wid * 32 + rh * 8 + g;
        ap[rh] = src + (size_t)row * (NSLOT * D_IN) + (size_t)slot * D_IN + t4 * 4;
    }

    float acc[2][2][4];
    #pragma unroll
    for (int mt = 0; mt < 2; mt++)
        #pragma unroll
        for (int nt = 0; nt < 2; nt++)
            #pragma unroll
            for (int jj = 0; jj < 4; jj++) acc[mt][nt][jj] = 0.0f;

    // prefetch chunk 0
    float4 f[4], pf[4];
    #pragma unroll
    for (int rh = 0; rh < 4; rh++) f[rh] = *(const float4*)(ap[rh]);

    #pragma unroll 2
    for (int c = 0; c < NCHK; c++) {
        // prefetch next chunk while computing this one
        if (c + 1 < NCHK) {
            #pragma unroll
            for (int rh = 0; rh < 4; rh++)
                pf[rh] = *(const float4*)(ap[rh] + (c + 1) * 16);
        }

        #pragma unroll
        for (int ks = 0; ks < 2; ks++) {
            // A fragments: a0=(g,t4), a1=(g+8,t4), a2=(g,t4+4), a3=(g+8,t4+4)
            uint32_t ah[2][4], al[2][4];
            #pragma unroll
            for (int mt = 0; mt < 2; mt++) {
                const float4 flo = f[2 * mt];
                const float4 fhi = f[2 * mt + 1];
                float e0 = ks ? flo.z : flo.x;
                float e1 = ks ? fhi.z : fhi.x;
                float e2 = ks ? flo.w : flo.y;
                float e3 = ks ? fhi.w : fhi.y;
                split2(e0, ah[mt][0], al[mt][0]);
                split2(e1, ah[mt][1], al[mt][1]);
                split2(e2, ah[mt][2], al[mt][2]);
                split2(e3, ah[mt][3], al[mt][3]);
            }
            #pragma unroll
            for (int nt = 0; nt < 2; nt++) {
                uint4 V = sFrag[((c * 2 + ks) * 2 + nt) * 32 + lane];
                #pragma unroll
                for (int mt = 0; mt < 2; mt++) {
                    mma16808(acc[mt][nt], ah[mt], V.x, V.y);   // hh
                    mma16808(acc[mt][nt], ah[mt], V.z, V.w);   // hl
                    mma16808(acc[mt][nt], al[mt], V.x, V.y);   // lh
                }
            }
        }

        #pragma unroll
        for (int rh = 0; rh < 4; rh++) f[rh] = pf[rh];
    }

    // write D: c0,c1 = row g cols t4*2,+1 ; c2,c3 = row g+8
    #pragma unroll
    for (int mt = 0; mt < 2; mt++) {
        int r0 = bbase + wid * 32 + mt * 16 + g;
        #pragma unroll
        for (int nt = 0; nt < 2; nt++) {
            int col = nt * 8 + t4 * 2;
            *(float2*)&g_P[v][r0][col]     = make_float2(acc[mt][nt][0], acc[mt][nt][1]);
            *(float2*)&g_P[v][r0 + 8][col] = make_float2(acc[mt][nt][2], acc[mt][nt][3]);
        }
    }
}

// ---------------------------------------------------------------------------
// Kernel 2: scores + threefry gumbel + argmax -> one-hot (2 threads per batch)
// ---------------------------------------------------------------------------
__device__ __forceinline__ uint32_t rotl32(uint32_t x, int r) {
    return (x << r) | (x >> (32 - r));
}

__device__ __forceinline__ uint32_t threefry_bits(uint32_t key, uint32_t ctr)
{
    const uint32_t ks0 = 0u, ks1 = key, ks2 = 0x1BD11BDAu ^ key;
    uint32_t x0 = ks0;
    uint32_t x1 = ctr + ks1;
#define R4(a,b,cc,d)                                   \
    x0 += x1; x1 = rotl32(x1,(a));  x1 ^= x0;          \
    x0 += x1; x1 = rotl32(x1,(b));  x1 ^= x0;          \
    x0 += x1; x1 = rotl32(x1,(cc)); x1 ^= x0;          \
    x0 += x1; x1 = rotl32(x1,(d));  x1 ^= x0;
    R4(13,15,26,6);   x0 += ks1; x1 += ks2 + 1u;
    R4(17,29,16,24);  x0 += ks2; x1 += ks0 + 2u;
    R4(13,15,26,6);   x0 += ks0; x1 += ks1 + 3u;
    R4(17,29,16,24);  x0 += ks1; x1 += ks2 + 4u;
    R4(13,15,26,6);   x0 += ks2; x1 += ks0 + 5u;
#undef R4
    return x0 ^ x1;
}

__device__ __forceinline__ float gumbel_from_bits(uint32_t bits)
{
    float u = __uint_as_float((bits >> 9) | 0x3f800000u) - 1.0f;
    float val = fmaxf(1e-10f, u * (1.0f - 1e-10f) + 1e-10f);
    return -logf(-logf(val));
}

__global__ __launch_bounds__(128) void score_kernel(float* __restrict__ out)
{
    const int idx = blockIdx.x * blockDim.x + threadIdx.x;
    const int b = idx >> 1;
    const int r = idx & 1;
    if (b >= B_TOTAL) return;

    float rv[DK];
    #pragma unroll
    for (int t = 0; t < 4; t++)
        ((float4*)rv)[t] = ((const float4*)&g_P[r][b][0])[t];

    float z[NSLOT];
    #pragma unroll
    for (int m = 0; m < NSLOT; m++) {
        float wv[DK];
        #pragma unroll
        for (int t = 0; t < 4; t++)
            ((float4*)wv)[t] = ((const float4*)&g_P[2 + m][b][0])[t];

        float s = 0.0f;
        #pragma unroll
        for (int t = 0; t < DK; t++) s = fmaf(rv[t], wv[t], s);
        s *= 0.25f;

        const uint32_t ctr = (uint32_t)(b * NSLOT + m);
        z[m] = s + gumbel_from_bits(threefry_bits(42u + (uint32_t)r, ctr));
    }

    int a0 = 0; float bv = z[0];
    #pragma unroll
    for (int m = 1; m < NSLOT; m++)
        if (z[m] > bv) { bv = z[m]; a0 = m; }

    float* o = out + (size_t)r * B_TOTAL * NSLOT + (size_t)b * NSLOT;
    #pragma unroll
    for (int m = 0; m < NSLOT; m++) o[m] = (m == a0) ? 1.0f : 0.0f;
}

// ---------------------------------------------------------------------------
extern "C" void kernel_launch(void* const* d_in, const int* in_sizes, int n_in,
                              void* d_out, int out_size)
{
    const float* q  = (const float*)d_in[0];
    const float* kk = (const float*)d_in[1];
    const float* wr = (const float*)d_in[2];
    const float* ww = (const float*)d_in[3];
    float* out = (float*)d_out;

    cudaFuncSetAttribute(proj_kernel,
                         cudaFuncAttributeMaxDynamicSharedMemorySize, SMEM_BYTES);

    dim3 grid1(B_TOTAL / MT, NV);
    proj_kernel<<<grid1, THREADS, SMEM_BYTES>>>(q, kk, wr, ww);

    score_kernel<<<(2 * B_TOTAL) / 128, 128>>>(out);
}

// round 13
// speedup vs baseline: 1.2677x; 1.1540x over previous
#include <cuda_runtime.h>
#include <cuda_fp16.h>
#include <cstdint>
#include <math.h>

#define B_TOTAL 32768
#define NSLOT   5
#define D_IN    512
#define DK      16
#define NV      7
#define MT      256          // batches per block
#define NCHK    (D_IN / 16)  // 32 k-chunks of 16
#define THREADS 256

// dynamic smem: sFrag only — [c][nt][lane] uint4 = 2048 * 16B = 32KB
#define SMEM_BYTES  32768

// projection scratch: P[v][b][k]; v: 0,1 = read slots; 2..6 = write slots
__device__ float g_P[NV][B_TOTAL][DK];

// fp16 2-way split of an fp32 pair, packed: h/l are f16x2 with e0 in low half.
// x = half(h) + half(l) + O(2^-22 x) residual after hh+hl+lh passes.
static __device__ __forceinline__ void split2h(float e0, float e1,
                                               uint32_t& h, uint32_t& l) {
    asm("cvt.rn.f16x2.f32 %0, %1, %2;" : "=r"(h) : "f"(e1), "f"(e0));
    __half2 hh = *reinterpret_cast<__half2*>(&h);
    float f0 = __half2float(__low2half(hh));
    float f1 = __half2float(__high2half(hh));
    asm("cvt.rn.f16x2.f32 %0, %1, %2;" : "=r"(l) : "f"(e1 - f1), "f"(e0 - f0));
}

static __device__ __forceinline__ void mma16816h(float* d, const uint32_t* a,
                                                 uint32_t b0, uint32_t b1) {
    asm volatile(
        "mma.sync.aligned.m16n8k16.row.col.f32.f16.f16.f32 "
        "{%0,%1,%2,%3}, {%4,%5,%6,%7}, {%8,%9}, {%0,%1,%2,%3};"
        : "+f"(d[0]), "+f"(d[1]), "+f"(d[2]), "+f"(d[3])
        : "r"(a[0]), "r"(a[1]), "r"(a[2]), "r"(a[3]), "r"(b0), "r"(b1));
}

// ---------------------------------------------------------------------------
// Kernel 1: projection GEMM on mma.m16n8k16.f16, fp32 via fp16 2-way split,
// 3 passes (hh, hl, lh). grid = (128, 7), 256 threads (8 warps x 32 batches).
//
// K-permutation: fragment slot (t4, half hf, elem e) <-> memory col
// d = c*16 + 4*t4 + 2*hf + e. A loads collapse to one float4 per (row,chunk):
// (x,y) -> half0 pair, (z,w) -> half1 pair. W converted gmem->fragment order:
// staging thread handles (c, t4f, n): reads W[d0..d0+3][n], packs
// {b0_h, b1_h, b0_l, b1_l} as uint4.
// ---------------------------------------------------------------------------
__global__ __launch_bounds__(THREADS, 3) void proj_kernel(
    const float* __restrict__ q, const float* __restrict__ kk,
    const float* __restrict__ wr, const float* __restrict__ ww)
{
    extern __shared__ uint32_t sh[];
    uint4* sFrag = (uint4*)sh;           // [c][nt][lane] -> {b0h, b1h, b0l, b1l}

    const int tid  = threadIdx.x;
    const int lane = tid & 31;
    const int wid  = tid >> 5;
    const int g    = lane >> 2;
    const int t4   = lane & 3;

    const int v = blockIdx.y;
    const float* src; const float* W; int slot;
    if (v < 2) { src = q;  slot = v;     W = wr + (size_t)v * D_IN * DK; }
    else       { src = kk; slot = v - 2; W = ww + (size_t)(v - 2) * D_IN * DK; }
    const int bbase = blockIdx.x * MT;

    // ---- W -> fragment conversion ----
    #pragma unroll
    for (int t = 0; t < 8; t++) {
        int s   = tid + t * THREADS;     // 0..2047
        int n   = s & 15;
        int grp = s >> 4;                // 0..127
        int c   = grp >> 2;
        int t4f = grp & 3;
        int d0  = c * 16 + 4 * t4f;
        float w0 = W[(d0 + 0) * DK + n];
        float w1 = W[(d0 + 1) * DK + n];
        float w2 = W[(d0 + 2) * DK + n];
        float w3 = W[(d0 + 3) * DK + n];
        uint4 V;
        split2h(w0, w1, V.x, V.z);       // b0 = cols (d0, d0+1)
        split2h(w2, w3, V.y, V.w);       // b1 = cols (d0+2, d0+3)
        int nt = n >> 3;
        int ln = (n & 7) * 4 + t4f;      // fragment lane = g*4 + t4
        sFrag[(c * 2 + nt) * 32 + ln] = V;
    }
    __syncthreads();

    // A pointers: warp rows wid*32 + {g, g+8, g+16, g+24}
    const float* ap[4];
    #pragma unroll
    for (int rh = 0; rh < 4; rh++) {
        int row = bbase + wid * 32 + rh * 8 + g;
        ap[rh] = src + (size_t)row * (NSLOT * D_IN) + (size_t)slot * D_IN + t4 * 4;
    }

    float acc[2][2][4];
    #pragma unroll
    for (int mt = 0; mt < 2; mt++)
        #pragma unroll
        for (int nt = 0; nt < 2; nt++)
            #pragma unroll
            for (int jj = 0; jj < 4; jj++) acc[mt][nt][jj] = 0.0f;

    // prefetch chunk 0
    float4 f[4], pf[4];
    #pragma unroll
    for (int rh = 0; rh < 4; rh++) f[rh] = *(const float4*)(ap[rh]);

    #pragma unroll 2
    for (int c = 0; c < NCHK; c++) {
        // prefetch next chunk while computing this one
        if (c + 1 < NCHK) {
            #pragma unroll
            for (int rh = 0; rh < 4; rh++)
                pf[rh] = *(const float4*)(ap[rh] + (c + 1) * 16);
        }

        // A fragments: per mt, regs a0..a3 (h) and low-plane copies
        //   a0 = (row g, half0), a1 = (row g+8, half0),
        //   a2 = (row g, half1), a3 = (row g+8, half1)
        uint32_t ah[2][4], al[2][4];
        #pragma unroll
        for (int mt = 0; mt < 2; mt++) {
            const float4 flo = f[2 * mt];
            const float4 fhi = f[2 * mt + 1];
            split2h(flo.x, flo.y, ah[mt][0], al[mt][0]);
            split2h(fhi.x, fhi.y, ah[mt][1], al[mt][1]);
            split2h(flo.z, flo.w, ah[mt][2], al[mt][2]);
            split2h(fhi.z, fhi.w, ah[mt][3], al[mt][3]);
        }

        #pragma unroll
        for (int nt = 0; nt < 2; nt++) {
            uint4 V = sFrag[(c * 2 + nt) * 32 + lane];
            #pragma unroll
            for (int mt = 0; mt < 2; mt++) {
                mma16816h(acc[mt][nt], ah[mt], V.x, V.y);   // hh
                mma16816h(acc[mt][nt], ah[mt], V.z, V.w);   // hl
                mma16816h(acc[mt][nt], al[mt], V.x, V.y);   // lh
                // ll dropped: 2^-22 relative, ~3e-8 abs on scores
            }
        }

        #pragma unroll
        for (int rh = 0; rh < 4; rh++) f[rh] = pf[rh];
    }

    // write D: c0,c1 = row g cols t4*2,+1 ; c2,c3 = row g+8
    #pragma unroll
    for (int mt = 0; mt < 2; mt++) {
        int r0 = bbase + wid * 32 + mt * 16 + g;
        #pragma unroll
        for (int nt = 0; nt < 2; nt++) {
            int col = nt * 8 + t4 * 2;
            *(float2*)&g_P[v][r0][col]     = make_float2(acc[mt][nt][0], acc[mt][nt][1]);
            *(float2*)&g_P[v][r0 + 8][col] = make_float2(acc[mt][nt][2], acc[mt][nt][3]);
        }
    }
}

// ---------------------------------------------------------------------------
// Kernel 2: scores + threefry gumbel + argmax -> one-hot (2 threads per batch)
// ---------------------------------------------------------------------------
__device__ __forceinline__ uint32_t rotl32(uint32_t x, int r) {
    return (x << r) | (x >> (32 - r));
}

__device__ __forceinline__ uint32_t threefry_bits(uint32_t key, uint32_t ctr)
{
    const uint32_t ks0 = 0u, ks1 = key, ks2 = 0x1BD11BDAu ^ key;
    uint32_t x0 = ks0;
    uint32_t x1 = ctr + ks1;
#define R4(a,b,cc,d)                                   \
    x0 += x1; x1 = rotl32(x1,(a));  x1 ^= x0;          \
    x0 += x1; x1 = rotl32(x1,(b));  x1 ^= x0;          \
    x0 += x1; x1 = rotl32(x1,(cc)); x1 ^= x0;          \
    x0 += x1; x1 = rotl32(x1,(d));  x1 ^= x0;
    R4(13,15,26,6);   x0 += ks1; x1 += ks2 + 1u;
    R4(17,29,16,24);  x0 += ks2; x1 += ks0 + 2u;
    R4(13,15,26,6);   x0 += ks0; x1 += ks1 + 3u;
    R4(17,29,16,24);  x0 += ks1; x1 += ks2 + 4u;
    R4(13,15,26,6);   x0 += ks2; x1 += ks0 + 5u;
#undef R4
    return x0 ^ x1;
}

__device__ __forceinline__ float gumbel_from_bits(uint32_t bits)
{
    float u = __uint_as_float((bits >> 9) | 0x3f800000u) - 1.0f;
    float val = fmaxf(1e-10f, u * (1.0f - 1e-10f) + 1e-10f);
    return -logf(-logf(val));
}

__global__ __launch_bounds__(128) void score_kernel(float* __restrict__ out)
{
    const int idx = blockIdx.x * blockDim.x + threadIdx.x;
    const int b = idx >> 1;
    const int r = idx & 1;
    if (b >= B_TOTAL) return;

    float rv[DK];
    #pragma unroll
    for (int t = 0; t < 4; t++)
        ((float4*)rv)[t] = ((const float4*)&g_P[r][b][0])[t];

    float z[NSLOT];
    #pragma unroll
    for (int m = 0; m < NSLOT; m++) {
        float wv[DK];
        #pragma unroll
        for (int t = 0; t < 4; t++)
            ((float4*)wv)[t] = ((const float4*)&g_P[2 + m][b][0])[t];

        float s = 0.0f;
        #pragma unroll
        for (int t = 0; t < DK; t++) s = fmaf(rv[t], wv[t], s);
        s *= 0.25f;

        const uint32_t ctr = (uint32_t)(b * NSLOT + m);
        z[m] = s + gumbel_from_bits(threefry_bits(42u + (uint32_t)r, ctr));
    }

    int a0 = 0; float bv = z[0];
    #pragma unroll
    for (int m = 1; m < NSLOT; m++)
        if (z[m] > bv) { bv = z[m]; a0 = m; }

    float* o = out + (size_t)r * B_TOTAL * NSLOT + (size_t)b * NSLOT;
    #pragma unroll
    for (int m = 0; m < NSLOT; m++) o[m] = (m == a0) ? 1.0f : 0.0f;
}

// ---------------------------------------------------------------------------
extern "C" void kernel_launch(void* const* d_in, const int* in_sizes, int n_in,
                              void* d_out, int out_size)
{
    const float* q  = (const float*)d_in[0];
    const float* kk = (const float*)d_in[1];
    const float* wr = (const float*)d_in[2];
    const float* ww = (const float*)d_in[3];
    float* out = (float*)d_out;

    cudaFuncSetAttribute(proj_kernel,
                         cudaFuncAttributeMaxDynamicSharedMemorySize, SMEM_BYTES);

    dim3 grid1(B_TOTAL / MT, NV);
    proj_kernel<<<grid1, THREADS, SMEM_BYTES>>>(q, kk, wr, ww);

    score_kernel<<<(2 * B_TOTAL) / 128, 128>>>(out);
}